// round 14
// baseline (speedup 1.0000x reference)
#include <cuda_runtime.h>
#include <cuda_bf16.h>
#include <cstdint>

#define N_NODES 100000
#define N_EDGES 1600000
#define FEAT 128
#define NCLS 47
#define SCAN_BLK 1024
#define N_SCAN_BLKS ((N_NODES + SCAN_BLK - 1) / SCAN_BLK)   // 98

// ---------------- scratch (no allocation allowed) ----------------
__device__ __align__(16) float g_h0[N_NODES * FEAT];
__device__ __align__(16) float g_h1[N_NODES * FEAT];
__device__ __align__(16) float g_mean[N_NODES * FEAT];
__device__ __align__(16) __nv_bfloat16 g_hb0[N_NODES * FEAT];
__device__ __align__(16) __nv_bfloat16 g_hb1[N_NODES * FEAT];
__device__ __align__(16) int g_cnt[N_NODES];      // zero-init; re-zeroed by fill each run
__device__ __align__(16) int g_off[N_NODES + 1];
__device__ __align__(16) int g_cur[N_NODES];
__device__ __align__(16) int g_esrc[N_EDGES];
__device__ __align__(16) int g_aggf[N_SCAN_BLKS]; // lookback flags; zero-init + fill re-zero

// ---------------- helpers ----------------
__device__ __forceinline__ uint32_t smem_u32(const void* p) {
    uint32_t a;
    asm("{ .reg .u64 t; cvta.to.shared.u64 t, %1; cvt.u32.u64 %0, t; }"
        : "=r"(a) : "l"(p));
    return a;
}
__device__ __forceinline__ void ldsm4(uint32_t* r, uint32_t a) {
    asm volatile("ldmatrix.sync.aligned.m8n8.x4.shared.b16 {%0,%1,%2,%3}, [%4];"
                 : "=r"(r[0]), "=r"(r[1]), "=r"(r[2]), "=r"(r[3]) : "r"(a));
}
__device__ __forceinline__ void ldsm4t(uint32_t* r, uint32_t a) {
    asm volatile("ldmatrix.sync.aligned.m8n8.x4.trans.shared.b16 {%0,%1,%2,%3}, [%4];"
                 : "=r"(r[0]), "=r"(r[1]), "=r"(r[2]), "=r"(r[3]) : "r"(a));
}
__device__ __forceinline__ void mma_bf16(float* d, const uint32_t* a, const uint32_t* b) {
    asm volatile(
        "mma.sync.aligned.m16n8k16.row.col.f32.bf16.bf16.f32 "
        "{%0,%1,%2,%3}, {%4,%5,%6,%7}, {%8,%9}, {%0,%1,%2,%3};"
        : "+f"(d[0]), "+f"(d[1]), "+f"(d[2]), "+f"(d[3])
        : "r"(a[0]), "r"(a[1]), "r"(a[2]), "r"(a[3]), "r"(b[0]), "r"(b[1]));
}
__device__ __forceinline__ void split_bf(float x, __nv_bfloat16& hi, __nv_bfloat16& lo) {
    hi = __float2bfloat16_rn(x);
    lo = __float2bfloat16_rn(x - __bfloat162float(hi));
}
__device__ __forceinline__ uint32_t pack_bf16x2(float lo_val, float hi_val) {
    __nv_bfloat162 t = __halves2bfloat162(__float2bfloat16_rn(lo_val),
                                          __float2bfloat16_rn(hi_val));
    return *reinterpret_cast<uint32_t*>(&t);
}
// accumulate 2 bf16 packed in u into a[0], a[1] using reinterpret tricks
__device__ __forceinline__ void acc_bf2(float& a0, float& a1, uint32_t u) {
    a0 += __uint_as_float(u << 16);
    a1 += __uint_as_float(u & 0xFFFF0000u);
}

// ---------------- launch 1: degree histogram + bf16 shadow of embeddings ----------------
__global__ void histprep_kernel(const float* __restrict__ embed,
                                __nv_bfloat16* __restrict__ hb0,
                                const int* __restrict__ dst,
                                int* __restrict__ cnt, int n4) {
    int i = blockIdx.x * blockDim.x + threadIdx.x;
    if (i < n4) {
        float4 v = reinterpret_cast<const float4*>(embed)[i];
        uint2 b;
        b.x = pack_bf16x2(v.x, v.y);
        b.y = pack_bf16x2(v.z, v.w);
        reinterpret_cast<uint2*>(hb0)[i] = b;
    }
    if (i < N_EDGES) atomicAdd(&cnt[dst[i]], 1);
}

// ---------------- launch 2: single-pass decoupled-lookback exclusive scan ----------------
__global__ void scan_lb_kernel(const int* __restrict__ cnt, int* __restrict__ off,
                               int* __restrict__ cur, int* __restrict__ aggf) {
    __shared__ int sh[SCAN_BLK];
    __shared__ int s_pref;
    int tid = threadIdx.x, b = blockIdx.x;
    int i = b * SCAN_BLK + tid;
    int v = (i < N_NODES) ? cnt[i] : 0;
    sh[tid] = v;
    __syncthreads();
#pragma unroll
    for (int o = 1; o < SCAN_BLK; o <<= 1) {
        int t = (tid >= o) ? sh[tid - o] : 0;
        __syncthreads();
        sh[tid] += t;
        __syncthreads();
    }
    if (tid == 0) ((volatile int*)aggf)[b] = sh[SCAN_BLK - 1] + 1;
    if (tid < 32) {
        int pref = 0;
        for (int base = b - 1; base >= 0; base -= 32) {
            int p = base - tid;
            int a = 0;
            if (p >= 0) {
                volatile int* f = (volatile int*)aggf + p;
                do { a = *f; } while (a == 0);
                a -= 1;
            }
#pragma unroll
            for (int s = 16; s; s >>= 1) a += __shfl_down_sync(0xffffffffu, a, s);
            if (tid == 0) pref += a;
        }
        if (tid == 0) s_pref = pref;
    }
    __syncthreads();
    int pref = s_pref;
    if (i < N_NODES) {
        int e = sh[tid] - v + pref;
        off[i] = e;
        cur[i] = e;
    }
    if (i == 0) off[N_NODES] = N_EDGES;
}

// ---------------- launch 3: CSR fill + re-zero cnt/flags ----------------
__global__ void fill_kernel(const int* __restrict__ src, const int* __restrict__ dst,
                            int* __restrict__ cur, int* __restrict__ esrc,
                            int* __restrict__ cnt, int* __restrict__ aggf) {
    int e = blockIdx.x * blockDim.x + threadIdx.x;
    if (e < N_EDGES) {
        int pos = atomicAdd(&cur[dst[e]], 1);
        esrc[pos] = src[e];
    }
    if (e < N_NODES) cnt[e] = 0;
    if (e < N_SCAN_BLKS) aggf[e] = 0;
}

// ---------------- CSR mean aggregation: 2 edges/warp-step, mask-convert ----------------
// Warp per node. Lane = (edge-parity l>>4, 16B-column l&15). Each lane loads a
// uint4 (8 bf16) per edge => one warp LDG.128 covers TWO edge rows. bf16->fp32
// via reinterpret (shl / and), fp32 accumulate, cross-parity shfl reduction.
__global__ void agg_kernel(const __nv_bfloat16* __restrict__ hb,
                           const int* __restrict__ esrc,
                           const int* __restrict__ off,
                           float* __restrict__ mean) {
    int t = blockIdx.x * blockDim.x + threadIdx.x;
    int v = t >> 5, l = t & 31;
    if (v >= N_NODES) return;
    int beg = off[v];
    int end = off[v + 1];
    int half = l >> 4;       // which edge of the pair
    int q = l & 15;          // 16B column within 256B row
    const uint4* H4 = reinterpret_cast<const uint4*>(hb);   // 16 uint4 per row

    float a0 = 0.f, a1 = 0.f, a2 = 0.f, a3 = 0.f;
    float a4 = 0.f, a5 = 0.f, a6 = 0.f, a7 = 0.f;

    int j = beg + half;
    // unroll 2 warp-steps: this lane handles edges j and j+2
    for (; j + 2 < end; j += 4) {
        int s0 = esrc[j];
        int s1 = esrc[j + 2];
        uint4 d0 = H4[s0 * 16 + q];
        uint4 d1 = H4[s1 * 16 + q];
        acc_bf2(a0, a1, d0.x); acc_bf2(a2, a3, d0.y);
        acc_bf2(a4, a5, d0.z); acc_bf2(a6, a7, d0.w);
        acc_bf2(a0, a1, d1.x); acc_bf2(a2, a3, d1.y);
        acc_bf2(a4, a5, d1.z); acc_bf2(a6, a7, d1.w);
    }
    for (; j < end; j += 2) {
        int s = esrc[j];
        uint4 d = H4[s * 16 + q];
        acc_bf2(a0, a1, d.x); acc_bf2(a2, a3, d.y);
        acc_bf2(a4, a5, d.z); acc_bf2(a6, a7, d.w);
    }

    // cross-parity reduction: lane l and l+16 hold the same features
    a0 += __shfl_down_sync(0xffffffffu, a0, 16);
    a1 += __shfl_down_sync(0xffffffffu, a1, 16);
    a2 += __shfl_down_sync(0xffffffffu, a2, 16);
    a3 += __shfl_down_sync(0xffffffffu, a3, 16);
    a4 += __shfl_down_sync(0xffffffffu, a4, 16);
    a5 += __shfl_down_sync(0xffffffffu, a5, 16);
    a6 += __shfl_down_sync(0xffffffffu, a6, 16);
    a7 += __shfl_down_sync(0xffffffffu, a7, 16);

    if (half == 0) {
        float invd = 1.0f / fmaxf((float)(end - beg), 1.0f);
        float4* M = reinterpret_cast<float4*>(mean);
        M[v * 32 + q * 2 + 0] = make_float4(a0 * invd, a1 * invd, a2 * invd, a3 * invd);
        M[v * 32 + q * 2 + 1] = make_float4(a4 * invd, a5 * invd, a6 * invd, a7 * invd);
    }
}

// ---------------- mma.sync dual GEMM (bf16 hi/lo split -> fp32 accuracy) ----------------
template <int BN, int NOUT, bool RELU, bool WB>
__global__ void __launch_bounds__(256) gemm_mma(
    const float* __restrict__ h, const float* __restrict__ mean,
    const float* __restrict__ Wn, const float* __restrict__ Ws,
    const float* __restrict__ bias, float* __restrict__ out,
    __nv_bfloat16* __restrict__ outb) {
    extern __shared__ char smem[];
    const uint32_t sb = smem_u32(smem);
    const int tid = threadIdx.x;
    const int wid = tid >> 5;
    const int lane = tid & 31;
    const int wm = wid >> 1;
    const int wn = wid & 1;
    const int r0 = blockIdx.x * 128;

    constexpr int HN = BN / 2;
    constexpr int NT = HN / 8;
    constexpr uint32_t A_HI = 1024;
    constexpr uint32_t A_LO = 1024 + 16384;
    constexpr uint32_t B_HI = 1024 + 32768;
    constexpr uint32_t B_LO = B_HI + (uint32_t)BN * 128;

    if (tid < NOUT) *reinterpret_cast<float*>(smem + tid * 4) = bias[tid];

    const float4* mean4 = reinterpret_cast<const float4*>(mean);
    const float4* h4 = reinterpret_cast<const float4*>(h);

    float acc[2][NT][4];
#pragma unroll
    for (int i = 0; i < 2; i++)
#pragma unroll
        for (int j = 0; j < NT; j++)
#pragma unroll
            for (int q = 0; q < 4; q++) acc[i][j][q] = 0.f;

    for (int c = 0; c < 4; c++) {
        __syncthreads();

        // ---- A chunk: 128 rows x 64 floats -> bf16 hi/lo ----
#pragma unroll
        for (int it = 0; it < 8; it++) {
            int idx = tid + it * 256;
            int m = idx >> 4;
            int q = idx & 15;
            int row = r0 + m;
            float4 v = make_float4(0.f, 0.f, 0.f, 0.f);
            if (row < N_NODES)
                v = (c < 2) ? mean4[row * 32 + c * 16 + q]
                            : h4[row * 32 + (c - 2) * 16 + q];
            __nv_bfloat16 h0b, h1b, h2b, h3b, l0b, l1b, l2b, l3b;
            split_bf(v.x, h0b, l0b);
            split_bf(v.y, h1b, l1b);
            split_bf(v.z, h2b, l2b);
            split_bf(v.w, h3b, l3b);
            uint32_t off = (uint32_t)(m * 128 + q * 8);
            off ^= (uint32_t)(m & 7) << 4;
            __nv_bfloat162 hh0 = __halves2bfloat162(h0b, h1b);
            __nv_bfloat162 hh1 = __halves2bfloat162(h2b, h3b);
            __nv_bfloat162 ll0 = __halves2bfloat162(l0b, l1b);
            __nv_bfloat162 ll1 = __halves2bfloat162(l2b, l3b);
            *reinterpret_cast<uint2*>(smem + A_HI + off) =
                make_uint2(*reinterpret_cast<uint32_t*>(&hh0), *reinterpret_cast<uint32_t*>(&hh1));
            *reinterpret_cast<uint2*>(smem + A_LO + off) =
                make_uint2(*reinterpret_cast<uint32_t*>(&ll0), *reinterpret_cast<uint32_t*>(&ll1));
        }

        // ---- B chunk: 64 k-rows x BN cols of W ----
        {
            const float* W = (c < 2) ? Wn : Ws;
            int kb = (c & 1) * 64;
            if (BN == 128 && NOUT == 128) {
                const float4* W4 = reinterpret_cast<const float4*>(W);
#pragma unroll
                for (int it = 0; it < 8; it++) {
                    int idx = tid + it * 256;
                    int k = idx >> 5;
                    int nq = idx & 31;
                    float4 v = W4[(kb + k) * 32 + nq];
                    __nv_bfloat16 h0b, h1b, h2b, h3b, l0b, l1b, l2b, l3b;
                    split_bf(v.x, h0b, l0b);
                    split_bf(v.y, h1b, l1b);
                    split_bf(v.z, h2b, l2b);
                    split_bf(v.w, h3b, l3b);
                    uint32_t off = (uint32_t)(k * 256 + nq * 8);
                    off ^= (uint32_t)(k & 7) << 4;
                    __nv_bfloat162 hh0 = __halves2bfloat162(h0b, h1b);
                    __nv_bfloat162 hh1 = __halves2bfloat162(h2b, h3b);
                    __nv_bfloat162 ll0 = __halves2bfloat162(l0b, l1b);
                    __nv_bfloat162 ll1 = __halves2bfloat162(l2b, l3b);
                    *reinterpret_cast<uint2*>(smem + B_HI + off) =
                        make_uint2(*reinterpret_cast<uint32_t*>(&hh0), *reinterpret_cast<uint32_t*>(&hh1));
                    *reinterpret_cast<uint2*>(smem + B_LO + off) =
                        make_uint2(*reinterpret_cast<uint32_t*>(&ll0), *reinterpret_cast<uint32_t*>(&ll1));
                }
            } else {
#pragma unroll
                for (int it = 0; it < BN * 64 / 256; it++) {
                    int idx = tid + it * 256;
                    int k = idx / BN;
                    int n = idx % BN;
                    float w = (n < NOUT) ? W[(kb + k) * NOUT + n] : 0.f;
                    __nv_bfloat16 hi, lo;
                    split_bf(w, hi, lo);
                    uint32_t off = (uint32_t)(k * BN * 2 + n * 2);
                    off ^= (uint32_t)(k & 7) << 4;
                    *reinterpret_cast<__nv_bfloat16*>(smem + B_HI + off) = hi;
                    *reinterpret_cast<__nv_bfloat16*>(smem + B_LO + off) = lo;
                }
            }
        }
        __syncthreads();

        // ---- compute: 4 k-steps of 16 ----
#pragma unroll
        for (int kt = 0; kt < 4; kt++) {
            uint32_t ah[2][4], al[2][4];
            int arow_base = wm * 32 + (lane & 15);
            int akb = kt * 32 + ((lane >> 4) << 4);
#pragma unroll
            for (int mt = 0; mt < 2; mt++) {
                int row = arow_base + mt * 16;
                uint32_t off = (uint32_t)(row * 128 + akb);
                off ^= (uint32_t)(row & 7) << 4;
                ldsm4(ah[mt], sb + A_HI + off);
                ldsm4(al[mt], sb + A_LO + off);
            }
            int bk = kt * 16 + (lane & 15);
#pragma unroll
            for (int np = 0; np < NT / 2; np++) {
                int n0 = wn * HN + np * 16 + ((lane >> 4) << 3);
                uint32_t off = (uint32_t)(bk * BN * 2 + n0 * 2);
                off ^= (uint32_t)(bk & 7) << 4;
                uint32_t bh[4], bl[4];
                ldsm4t(bh, sb + B_HI + off);
                ldsm4t(bl, sb + B_LO + off);
#pragma unroll
                for (int hh = 0; hh < 2; hh++) {
                    int nt = np * 2 + hh;
#pragma unroll
                    for (int mt = 0; mt < 2; mt++) {
                        mma_bf16(acc[mt][nt], ah[mt], bh + 2 * hh);
                        mma_bf16(acc[mt][nt], ah[mt], bl + 2 * hh);
                        mma_bf16(acc[mt][nt], al[mt], bh + 2 * hh);
                    }
                }
            }
        }
    }

    // ---- epilogue: stage through SMEM for coalesced global writes ----
    const float* biasS = reinterpret_cast<const float*>(smem);
    __syncthreads();
    float* D = reinterpret_cast<float*>(smem + 1024);

    if (BN == 128) {
#pragma unroll
        for (int mt = 0; mt < 2; mt++) {
#pragma unroll
            for (int nt = 0; nt < NT; nt++) {
                int col = wn * HN + nt * 8 + (lane & 3) * 2;
#pragma unroll
                for (int p = 0; p < 2; p++) {
                    int rl = wm * 32 + mt * 16 + (lane >> 2) + p * 8;
                    float w0 = acc[mt][nt][2 * p + 0] + biasS[col];
                    float w1 = acc[mt][nt][2 * p + 1] + biasS[col + 1];
                    if (RELU) { w0 = fmaxf(w0, 0.f); w1 = fmaxf(w1, 0.f); }
                    int cs = col ^ ((rl & 7) << 3);
                    *reinterpret_cast<float2*>(&D[rl * 128 + cs]) = make_float2(w0, w1);
                }
            }
        }
        __syncthreads();
#pragma unroll
        for (int it = 0; it < 16; it++) {
            int idx = tid + it * 256;
            int rl = idx >> 5;
            int q = idx & 31;
            int r = r0 + rl;
            if (r < N_NODES) {
                int cs = (q * 4) ^ ((rl & 7) << 3);
                float4 v = *reinterpret_cast<float4*>(&D[rl * 128 + cs]);
                reinterpret_cast<float4*>(out)[(size_t)r * 32 + q] = v;
                if (WB) {
                    uint2 b;
                    b.x = pack_bf16x2(v.x, v.y);
                    b.y = pack_bf16x2(v.z, v.w);
                    reinterpret_cast<uint2*>(outb)[(size_t)r * 32 + q] = b;
                }
            }
        }
    } else {
        constexpr int STRIDE = 66;
#pragma unroll
        for (int mt = 0; mt < 2; mt++) {
#pragma unroll
            for (int nt = 0; nt < NT; nt++) {
                int col = wn * HN + nt * 8 + (lane & 3) * 2;
#pragma unroll
                for (int p = 0; p < 2; p++) {
                    int rl = wm * 32 + mt * 16 + (lane >> 2) + p * 8;
                    if (col < NOUT) {
                        float w0 = acc[mt][nt][2 * p + 0] + biasS[col];
                        if (RELU) w0 = fmaxf(w0, 0.f);
                        D[rl * STRIDE + col] = w0;
                    }
                    if (col + 1 < NOUT) {
                        float w1 = acc[mt][nt][2 * p + 1] + biasS[col + 1];
                        if (RELU) w1 = fmaxf(w1, 0.f);
                        D[rl * STRIDE + col + 1] = w1;
                    }
                }
            }
        }
        __syncthreads();
        int nrows = N_NODES - r0;
        if (nrows > 128) nrows = 128;
        int total = nrows * NOUT;
        for (int e = tid; e < total; e += 256) {
            int rl = e / NOUT;
            int cc = e - rl * NOUT;
            out[(size_t)(r0) * NOUT + e] = D[rl * STRIDE + cc];
        }
    }
}

// ---------------- launch ----------------
extern "C" void kernel_launch(void* const* d_in, const int* in_sizes, int n_in,
                              void* d_out, int out_size) {
    const float* embed  = (const float*)d_in[0];
    const float* Wself0 = (const float*)d_in[1];
    const float* Wneigh0= (const float*)d_in[2];
    const float* b0     = (const float*)d_in[3];
    const float* Wself1 = (const float*)d_in[4];
    const float* Wneigh1= (const float*)d_in[5];
    const float* b1     = (const float*)d_in[6];
    const float* Wself2 = (const float*)d_in[7];
    const float* Wneigh2= (const float*)d_in[8];
    const float* b2     = (const float*)d_in[9];
    const int* src      = (const int*)d_in[11];
    const int* dst      = (const int*)d_in[12];
    float* out = (float*)d_out;

    float *h0, *h1, *mean;
    __nv_bfloat16 *hb0, *hb1;
    int *cnt, *off, *cur, *esrc, *aggf;
    cudaGetSymbolAddress((void**)&h0, g_h0);
    cudaGetSymbolAddress((void**)&h1, g_h1);
    cudaGetSymbolAddress((void**)&mean, g_mean);
    cudaGetSymbolAddress((void**)&hb0, g_hb0);
    cudaGetSymbolAddress((void**)&hb1, g_hb1);
    cudaGetSymbolAddress((void**)&cnt, g_cnt);
    cudaGetSymbolAddress((void**)&off, g_off);
    cudaGetSymbolAddress((void**)&cur, g_cur);
    cudaGetSymbolAddress((void**)&esrc, g_esrc);
    cudaGetSymbolAddress((void**)&aggf, g_aggf);

    const int T = 256;
    const int gemm_blocks = (N_NODES + 127) / 128;           // 782
    const int warp_blocks = (N_NODES * 32 + T - 1) / T;
    const int nf4 = N_NODES * 32;

    const int SMEM_128 = 1024 + 32768 + 2 * 128 * 128;       // 66560
    const int SMEM_64  = 1024 + 128 * 66 * 4;
    const int SMEM_64_REAL = (SMEM_64 > (1024 + 32768 + 2 * 64 * 128))
                                 ? SMEM_64 : (1024 + 32768 + 2 * 64 * 128);
    cudaFuncSetAttribute(gemm_mma<128, 128, true, true>,
                         cudaFuncAttributeMaxDynamicSharedMemorySize, SMEM_128);
    cudaFuncSetAttribute(gemm_mma<64, NCLS, false, false>,
                         cudaFuncAttributeMaxDynamicSharedMemorySize, SMEM_64_REAL);

    // 1: histogram + shadow
    histprep_kernel<<<(nf4 + T - 1) / T, T>>>(embed, hb0, dst, cnt, nf4);
    // 2: single-pass exclusive scan (decoupled lookback)
    scan_lb_kernel<<<N_SCAN_BLKS, SCAN_BLK>>>(cnt, off, cur, aggf);
    // 3: CSR fill + re-zero cnt/flags
    fill_kernel<<<(N_EDGES + T - 1) / T, T>>>(src, dst, cur, esrc, cnt, aggf);

    // 4 (ncu-captured): layer 0 aggregation
    agg_kernel<<<warp_blocks, T>>>(hb0, esrc, off, mean);
    // 5: layer 0 GEMM: embed -> h1 (relu)
    gemm_mma<128, 128, true, true><<<gemm_blocks, T, SMEM_128>>>(
        embed, mean, Wneigh0, Wself0, b0, h1, hb1);

    // 6-7: layer 1: h1 -> h0 (relu)
    agg_kernel<<<warp_blocks, T>>>(hb1, esrc, off, mean);
    gemm_mma<128, 128, true, true><<<gemm_blocks, T, SMEM_128>>>(
        h1, mean, Wneigh1, Wself1, b1, h0, hb0);

    // 8-9: layer 2: h0 -> out (no relu, 47 classes)
    agg_kernel<<<warp_blocks, T>>>(hb0, esrc, off, mean);
    gemm_mma<64, NCLS, false, false><<<gemm_blocks, T, SMEM_64_REAL>>>(
        h0, mean, Wneigh2, Wself2, b2, out, nullptr);
}

// round 15
// speedup vs baseline: 1.0775x; 1.0775x over previous
#include <cuda_runtime.h>
#include <cuda_bf16.h>
#include <cstdint>

#define N_NODES 100000
#define N_EDGES 1600000
#define FEAT 128
#define NCLS 47
#define SCAN_BLK 1024
#define N_SCAN_BLKS ((N_NODES + SCAN_BLK - 1) / SCAN_BLK)   // 98

// ---------------- scratch (no allocation allowed) ----------------
__device__ __align__(16) float g_h0[N_NODES * FEAT];
__device__ __align__(16) float g_h1[N_NODES * FEAT];
__device__ __align__(16) float g_mean[N_NODES * FEAT];
__device__ __align__(16) __nv_bfloat16 g_hb0[N_NODES * FEAT];
__device__ __align__(16) __nv_bfloat16 g_hb1[N_NODES * FEAT];
__device__ __align__(16) int g_cnt[N_NODES];      // zero-init; re-zeroed by fill each run
__device__ __align__(16) int g_off[N_NODES + 1];
__device__ __align__(16) int g_cur[N_NODES];
__device__ __align__(16) int g_esrc[N_EDGES];
__device__ __align__(16) int g_aggf[N_SCAN_BLKS]; // lookback flags; zero-init + fill re-zero

// ---------------- helpers ----------------
__device__ __forceinline__ uint32_t smem_u32(const void* p) {
    uint32_t a;
    asm("{ .reg .u64 t; cvta.to.shared.u64 t, %1; cvt.u32.u64 %0, t; }"
        : "=r"(a) : "l"(p));
    return a;
}
__device__ __forceinline__ void ldsm4(uint32_t* r, uint32_t a) {
    asm volatile("ldmatrix.sync.aligned.m8n8.x4.shared.b16 {%0,%1,%2,%3}, [%4];"
                 : "=r"(r[0]), "=r"(r[1]), "=r"(r[2]), "=r"(r[3]) : "r"(a));
}
__device__ __forceinline__ void ldsm4t(uint32_t* r, uint32_t a) {
    asm volatile("ldmatrix.sync.aligned.m8n8.x4.trans.shared.b16 {%0,%1,%2,%3}, [%4];"
                 : "=r"(r[0]), "=r"(r[1]), "=r"(r[2]), "=r"(r[3]) : "r"(a));
}
__device__ __forceinline__ void mma_bf16(float* d, const uint32_t* a, const uint32_t* b) {
    asm volatile(
        "mma.sync.aligned.m16n8k16.row.col.f32.bf16.bf16.f32 "
        "{%0,%1,%2,%3}, {%4,%5,%6,%7}, {%8,%9}, {%0,%1,%2,%3};"
        : "+f"(d[0]), "+f"(d[1]), "+f"(d[2]), "+f"(d[3])
        : "r"(a[0]), "r"(a[1]), "r"(a[2]), "r"(a[3]), "r"(b[0]), "r"(b[1]));
}
__device__ __forceinline__ void split_bf(float x, __nv_bfloat16& hi, __nv_bfloat16& lo) {
    hi = __float2bfloat16_rn(x);
    lo = __float2bfloat16_rn(x - __bfloat162float(hi));
}
__device__ __forceinline__ uint32_t pack_bf16x2(float lo_val, float hi_val) {
    __nv_bfloat162 t = __halves2bfloat162(__float2bfloat16_rn(lo_val),
                                          __float2bfloat16_rn(hi_val));
    return *reinterpret_cast<uint32_t*>(&t);
}
// accumulate 2 bf16 packed in u (lo half = feature0, hi half = feature1):
// bf16 is the top 16 bits of fp32, so shift/mask reinterpret is EXACT.
__device__ __forceinline__ void acc_bf2(float& a0, float& a1, uint32_t u) {
    a0 += __uint_as_float(u << 16);
    a1 += __uint_as_float(u & 0xFFFF0000u);
}

// ---------------- launch 1: degree histogram + bf16 shadow of embeddings ----------------
__global__ void histprep_kernel(const float* __restrict__ embed,
                                __nv_bfloat16* __restrict__ hb0,
                                const int* __restrict__ dst,
                                int* __restrict__ cnt, int n4) {
    int i = blockIdx.x * blockDim.x + threadIdx.x;
    if (i < n4) {
        float4 v = reinterpret_cast<const float4*>(embed)[i];
        uint2 b;
        b.x = pack_bf16x2(v.x, v.y);
        b.y = pack_bf16x2(v.z, v.w);
        reinterpret_cast<uint2*>(hb0)[i] = b;
    }
    if (i < N_EDGES) atomicAdd(&cnt[dst[i]], 1);
}

// ---------------- launch 2: single-pass decoupled-lookback exclusive scan ----------------
__global__ void scan_lb_kernel(const int* __restrict__ cnt, int* __restrict__ off,
                               int* __restrict__ cur, int* __restrict__ aggf) {
    __shared__ int sh[SCAN_BLK];
    __shared__ int s_pref;
    int tid = threadIdx.x, b = blockIdx.x;
    int i = b * SCAN_BLK + tid;
    int v = (i < N_NODES) ? cnt[i] : 0;
    sh[tid] = v;
    __syncthreads();
#pragma unroll
    for (int o = 1; o < SCAN_BLK; o <<= 1) {
        int t = (tid >= o) ? sh[tid - o] : 0;
        __syncthreads();
        sh[tid] += t;
        __syncthreads();
    }
    if (tid == 0) ((volatile int*)aggf)[b] = sh[SCAN_BLK - 1] + 1;
    if (tid < 32) {
        int pref = 0;
        for (int base = b - 1; base >= 0; base -= 32) {
            int p = base - tid;
            int a = 0;
            if (p >= 0) {
                volatile int* f = (volatile int*)aggf + p;
                do { a = *f; } while (a == 0);
                a -= 1;
            }
#pragma unroll
            for (int s = 16; s; s >>= 1) a += __shfl_down_sync(0xffffffffu, a, s);
            if (tid == 0) pref += a;
        }
        if (tid == 0) s_pref = pref;
    }
    __syncthreads();
    int pref = s_pref;
    if (i < N_NODES) {
        int e = sh[tid] - v + pref;
        off[i] = e;
        cur[i] = e;
    }
    if (i == 0) off[N_NODES] = N_EDGES;
}

// ---------------- launch 3: CSR fill + re-zero cnt/flags ----------------
__global__ void fill_kernel(const int* __restrict__ src, const int* __restrict__ dst,
                            int* __restrict__ cur, int* __restrict__ esrc,
                            int* __restrict__ cnt, int* __restrict__ aggf) {
    int e = blockIdx.x * blockDim.x + threadIdx.x;
    if (e < N_EDGES) {
        int pos = atomicAdd(&cur[dst[e]], 1);
        esrc[pos] = src[e];
    }
    if (e < N_NODES) cnt[e] = 0;
    if (e < N_SCAN_BLKS) aggf[e] = 0;
}

// ---------------- CSR mean aggregation (R13 structure + mask-convert accumulate) ----------------
__global__ void agg_kernel(const __nv_bfloat16* __restrict__ hb,
                           const int* __restrict__ esrc,
                           const int* __restrict__ off,
                           float* __restrict__ mean) {
    int t = blockIdx.x * blockDim.x + threadIdx.x;
    int v = t >> 5, l = t & 31;
    if (v >= N_NODES) return;
    int beg = off[v];
    int end = off[v + 1];
    const uint2* hb2 = reinterpret_cast<const uint2*>(hb);
    float ax = 0.f, ay = 0.f, az = 0.f, aw = 0.f;
    int j = beg;
    for (; j + 4 <= end; j += 4) {
        int s0 = esrc[j], s1 = esrc[j + 1], s2 = esrc[j + 2], s3 = esrc[j + 3];
        uint2 d0 = hb2[s0 * 32 + l];
        uint2 d1 = hb2[s1 * 32 + l];
        uint2 d2 = hb2[s2 * 32 + l];
        uint2 d3 = hb2[s3 * 32 + l];
        acc_bf2(ax, ay, d0.x); acc_bf2(az, aw, d0.y);
        acc_bf2(ax, ay, d1.x); acc_bf2(az, aw, d1.y);
        acc_bf2(ax, ay, d2.x); acc_bf2(az, aw, d2.y);
        acc_bf2(ax, ay, d3.x); acc_bf2(az, aw, d3.y);
    }
    for (; j < end; j++) {
        uint2 d = hb2[esrc[j] * 32 + l];
        acc_bf2(ax, ay, d.x);
        acc_bf2(az, aw, d.y);
    }
    float invd = 1.0f / fmaxf((float)(end - beg), 1.0f);
    reinterpret_cast<float4*>(mean)[v * 32 + l] =
        make_float4(ax * invd, ay * invd, az * invd, aw * invd);
}

// ---------------- mma.sync dual GEMM (bf16 hi/lo split -> fp32 accuracy) ----------------
template <int BN, int NOUT, bool RELU, bool WB>
__global__ void __launch_bounds__(256) gemm_mma(
    const float* __restrict__ h, const float* __restrict__ mean,
    const float* __restrict__ Wn, const float* __restrict__ Ws,
    const float* __restrict__ bias, float* __restrict__ out,
    __nv_bfloat16* __restrict__ outb) {
    extern __shared__ char smem[];
    const uint32_t sb = smem_u32(smem);
    const int tid = threadIdx.x;
    const int wid = tid >> 5;
    const int lane = tid & 31;
    const int wm = wid >> 1;
    const int wn = wid & 1;
    const int r0 = blockIdx.x * 128;

    constexpr int HN = BN / 2;
    constexpr int NT = HN / 8;
    constexpr uint32_t A_HI = 1024;
    constexpr uint32_t A_LO = 1024 + 16384;
    constexpr uint32_t B_HI = 1024 + 32768;
    constexpr uint32_t B_LO = B_HI + (uint32_t)BN * 128;

    if (tid < NOUT) *reinterpret_cast<float*>(smem + tid * 4) = bias[tid];

    const float4* mean4 = reinterpret_cast<const float4*>(mean);
    const float4* h4 = reinterpret_cast<const float4*>(h);

    float acc[2][NT][4];
#pragma unroll
    for (int i = 0; i < 2; i++)
#pragma unroll
        for (int j = 0; j < NT; j++)
#pragma unroll
            for (int q = 0; q < 4; q++) acc[i][j][q] = 0.f;

    for (int c = 0; c < 4; c++) {
        __syncthreads();

        // ---- A chunk: 128 rows x 64 floats -> bf16 hi/lo ----
#pragma unroll
        for (int it = 0; it < 8; it++) {
            int idx = tid + it * 256;
            int m = idx >> 4;
            int q = idx & 15;
            int row = r0 + m;
            float4 v = make_float4(0.f, 0.f, 0.f, 0.f);
            if (row < N_NODES)
                v = (c < 2) ? mean4[row * 32 + c * 16 + q]
                            : h4[row * 32 + (c - 2) * 16 + q];
            __nv_bfloat16 h0b, h1b, h2b, h3b, l0b, l1b, l2b, l3b;
            split_bf(v.x, h0b, l0b);
            split_bf(v.y, h1b, l1b);
            split_bf(v.z, h2b, l2b);
            split_bf(v.w, h3b, l3b);
            uint32_t off = (uint32_t)(m * 128 + q * 8);
            off ^= (uint32_t)(m & 7) << 4;
            __nv_bfloat162 hh0 = __halves2bfloat162(h0b, h1b);
            __nv_bfloat162 hh1 = __halves2bfloat162(h2b, h3b);
            __nv_bfloat162 ll0 = __halves2bfloat162(l0b, l1b);
            __nv_bfloat162 ll1 = __halves2bfloat162(l2b, l3b);
            *reinterpret_cast<uint2*>(smem + A_HI + off) =
                make_uint2(*reinterpret_cast<uint32_t*>(&hh0), *reinterpret_cast<uint32_t*>(&hh1));
            *reinterpret_cast<uint2*>(smem + A_LO + off) =
                make_uint2(*reinterpret_cast<uint32_t*>(&ll0), *reinterpret_cast<uint32_t*>(&ll1));
        }

        // ---- B chunk: 64 k-rows x BN cols of W ----
        {
            const float* W = (c < 2) ? Wn : Ws;
            int kb = (c & 1) * 64;
            if (BN == 128 && NOUT == 128) {
                const float4* W4 = reinterpret_cast<const float4*>(W);
#pragma unroll
                for (int it = 0; it < 8; it++) {
                    int idx = tid + it * 256;
                    int k = idx >> 5;
                    int nq = idx & 31;
                    float4 v = W4[(kb + k) * 32 + nq];
                    __nv_bfloat16 h0b, h1b, h2b, h3b, l0b, l1b, l2b, l3b;
                    split_bf(v.x, h0b, l0b);
                    split_bf(v.y, h1b, l1b);
                    split_bf(v.z, h2b, l2b);
                    split_bf(v.w, h3b, l3b);
                    uint32_t off = (uint32_t)(k * 256 + nq * 8);
                    off ^= (uint32_t)(k & 7) << 4;
                    __nv_bfloat162 hh0 = __halves2bfloat162(h0b, h1b);
                    __nv_bfloat162 hh1 = __halves2bfloat162(h2b, h3b);
                    __nv_bfloat162 ll0 = __halves2bfloat162(l0b, l1b);
                    __nv_bfloat162 ll1 = __halves2bfloat162(l2b, l3b);
                    *reinterpret_cast<uint2*>(smem + B_HI + off) =
                        make_uint2(*reinterpret_cast<uint32_t*>(&hh0), *reinterpret_cast<uint32_t*>(&hh1));
                    *reinterpret_cast<uint2*>(smem + B_LO + off) =
                        make_uint2(*reinterpret_cast<uint32_t*>(&ll0), *reinterpret_cast<uint32_t*>(&ll1));
                }
            } else {
#pragma unroll
                for (int it = 0; it < BN * 64 / 256; it++) {
                    int idx = tid + it * 256;
                    int k = idx / BN;
                    int n = idx % BN;
                    float w = (n < NOUT) ? W[(kb + k) * NOUT + n] : 0.f;
                    __nv_bfloat16 hi, lo;
                    split_bf(w, hi, lo);
                    uint32_t off = (uint32_t)(k * BN * 2 + n * 2);
                    off ^= (uint32_t)(k & 7) << 4;
                    *reinterpret_cast<__nv_bfloat16*>(smem + B_HI + off) = hi;
                    *reinterpret_cast<__nv_bfloat16*>(smem + B_LO + off) = lo;
                }
            }
        }
        __syncthreads();

        // ---- compute: 4 k-steps of 16 ----
#pragma unroll
        for (int kt = 0; kt < 4; kt++) {
            uint32_t ah[2][4], al[2][4];
            int arow_base = wm * 32 + (lane & 15);
            int akb = kt * 32 + ((lane >> 4) << 4);
#pragma unroll
            for (int mt = 0; mt < 2; mt++) {
                int row = arow_base + mt * 16;
                uint32_t off = (uint32_t)(row * 128 + akb);
                off ^= (uint32_t)(row & 7) << 4;
                ldsm4(ah[mt], sb + A_HI + off);
                ldsm4(al[mt], sb + A_LO + off);
            }
            int bk = kt * 16 + (lane & 15);
#pragma unroll
            for (int np = 0; np < NT / 2; np++) {
                int n0 = wn * HN + np * 16 + ((lane >> 4) << 3);
                uint32_t off = (uint32_t)(bk * BN * 2 + n0 * 2);
                off ^= (uint32_t)(bk & 7) << 4;
                uint32_t bh[4], bl[4];
                ldsm4t(bh, sb + B_HI + off);
                ldsm4t(bl, sb + B_LO + off);
#pragma unroll
                for (int hh = 0; hh < 2; hh++) {
                    int nt = np * 2 + hh;
#pragma unroll
                    for (int mt = 0; mt < 2; mt++) {
                        mma_bf16(acc[mt][nt], ah[mt], bh + 2 * hh);
                        mma_bf16(acc[mt][nt], ah[mt], bl + 2 * hh);
                        mma_bf16(acc[mt][nt], al[mt], bh + 2 * hh);
                    }
                }
            }
        }
    }

    // ---- epilogue: stage through SMEM for coalesced global writes ----
    const float* biasS = reinterpret_cast<const float*>(smem);
    __syncthreads();
    float* D = reinterpret_cast<float*>(smem + 1024);

    if (BN == 128) {
#pragma unroll
        for (int mt = 0; mt < 2; mt++) {
#pragma unroll
            for (int nt = 0; nt < NT; nt++) {
                int col = wn * HN + nt * 8 + (lane & 3) * 2;
#pragma unroll
                for (int p = 0; p < 2; p++) {
                    int rl = wm * 32 + mt * 16 + (lane >> 2) + p * 8;
                    float w0 = acc[mt][nt][2 * p + 0] + biasS[col];
                    float w1 = acc[mt][nt][2 * p + 1] + biasS[col + 1];
                    if (RELU) { w0 = fmaxf(w0, 0.f); w1 = fmaxf(w1, 0.f); }
                    int cs = col ^ ((rl & 7) << 3);
                    *reinterpret_cast<float2*>(&D[rl * 128 + cs]) = make_float2(w0, w1);
                }
            }
        }
        __syncthreads();
#pragma unroll
        for (int it = 0; it < 16; it++) {
            int idx = tid + it * 256;
            int rl = idx >> 5;
            int q = idx & 31;
            int r = r0 + rl;
            if (r < N_NODES) {
                int cs = (q * 4) ^ ((rl & 7) << 3);
                float4 v = *reinterpret_cast<float4*>(&D[rl * 128 + cs]);
                reinterpret_cast<float4*>(out)[(size_t)r * 32 + q] = v;
                if (WB) {
                    uint2 b;
                    b.x = pack_bf16x2(v.x, v.y);
                    b.y = pack_bf16x2(v.z, v.w);
                    reinterpret_cast<uint2*>(outb)[(size_t)r * 32 + q] = b;
                }
            }
        }
    } else {
        constexpr int STRIDE = 66;
#pragma unroll
        for (int mt = 0; mt < 2; mt++) {
#pragma unroll
            for (int nt = 0; nt < NT; nt++) {
                int col = wn * HN + nt * 8 + (lane & 3) * 2;
#pragma unroll
                for (int p = 0; p < 2; p++) {
                    int rl = wm * 32 + mt * 16 + (lane >> 2) + p * 8;
                    if (col < NOUT) {
                        float w0 = acc[mt][nt][2 * p + 0] + biasS[col];
                        if (RELU) w0 = fmaxf(w0, 0.f);
                        D[rl * STRIDE + col] = w0;
                    }
                    if (col + 1 < NOUT) {
                        float w1 = acc[mt][nt][2 * p + 1] + biasS[col + 1];
                        if (RELU) w1 = fmaxf(w1, 0.f);
                        D[rl * STRIDE + col + 1] = w1;
                    }
                }
            }
        }
        __syncthreads();
        int nrows = N_NODES - r0;
        if (nrows > 128) nrows = 128;
        int total = nrows * NOUT;
        for (int e = tid; e < total; e += 256) {
            int rl = e / NOUT;
            int cc = e - rl * NOUT;
            out[(size_t)(r0) * NOUT + e] = D[rl * STRIDE + cc];
        }
    }
}

// ---------------- launch ----------------
extern "C" void kernel_launch(void* const* d_in, const int* in_sizes, int n_in,
                              void* d_out, int out_size) {
    const float* embed  = (const float*)d_in[0];
    const float* Wself0 = (const float*)d_in[1];
    const float* Wneigh0= (const float*)d_in[2];
    const float* b0     = (const float*)d_in[3];
    const float* Wself1 = (const float*)d_in[4];
    const float* Wneigh1= (const float*)d_in[5];
    const float* b1     = (const float*)d_in[6];
    const float* Wself2 = (const float*)d_in[7];
    const float* Wneigh2= (const float*)d_in[8];
    const float* b2     = (const float*)d_in[9];
    const int* src      = (const int*)d_in[11];
    const int* dst      = (const int*)d_in[12];
    float* out = (float*)d_out;

    float *h0, *h1, *mean;
    __nv_bfloat16 *hb0, *hb1;
    int *cnt, *off, *cur, *esrc, *aggf;
    cudaGetSymbolAddress((void**)&h0, g_h0);
    cudaGetSymbolAddress((void**)&h1, g_h1);
    cudaGetSymbolAddress((void**)&mean, g_mean);
    cudaGetSymbolAddress((void**)&hb0, g_hb0);
    cudaGetSymbolAddress((void**)&hb1, g_hb1);
    cudaGetSymbolAddress((void**)&cnt, g_cnt);
    cudaGetSymbolAddress((void**)&off, g_off);
    cudaGetSymbolAddress((void**)&cur, g_cur);
    cudaGetSymbolAddress((void**)&esrc, g_esrc);
    cudaGetSymbolAddress((void**)&aggf, g_aggf);

    const int T = 256;
    const int gemm_blocks = (N_NODES + 127) / 128;           // 782
    const int warp_blocks = (N_NODES * 32 + T - 1) / T;
    const int nf4 = N_NODES * 32;

    const int SMEM_128 = 1024 + 32768 + 2 * 128 * 128;       // 66560
    const int SMEM_64  = 1024 + 128 * 66 * 4;
    const int SMEM_64_REAL = (SMEM_64 > (1024 + 32768 + 2 * 64 * 128))
                                 ? SMEM_64 : (1024 + 32768 + 2 * 64 * 128);
    cudaFuncSetAttribute(gemm_mma<128, 128, true, true>,
                         cudaFuncAttributeMaxDynamicSharedMemorySize, SMEM_128);
    cudaFuncSetAttribute(gemm_mma<64, NCLS, false, false>,
                         cudaFuncAttributeMaxDynamicSharedMemorySize, SMEM_64_REAL);

    // 1: histogram + shadow
    histprep_kernel<<<(nf4 + T - 1) / T, T>>>(embed, hb0, dst, cnt, nf4);
    // 2: single-pass exclusive scan (decoupled lookback)
    scan_lb_kernel<<<N_SCAN_BLKS, SCAN_BLK>>>(cnt, off, cur, aggf);
    // 3: CSR fill + re-zero cnt/flags
    fill_kernel<<<(N_EDGES + T - 1) / T, T>>>(src, dst, cur, esrc, cnt, aggf);

    // 4 (ncu-captured): layer 0 aggregation
    agg_kernel<<<warp_blocks, T>>>(hb0, esrc, off, mean);
    // 5: layer 0 GEMM: embed -> h1 (relu)
    gemm_mma<128, 128, true, true><<<gemm_blocks, T, SMEM_128>>>(
        embed, mean, Wneigh0, Wself0, b0, h1, hb1);

    // 6-7: layer 1: h1 -> h0 (relu)
    agg_kernel<<<warp_blocks, T>>>(hb1, esrc, off, mean);
    gemm_mma<128, 128, true, true><<<gemm_blocks, T, SMEM_128>>>(
        h1, mean, Wneigh1, Wself1, b1, h0, hb0);

    // 8-9: layer 2: h0 -> out (no relu, 47 classes)
    agg_kernel<<<warp_blocks, T>>>(hb0, esrc, off, mean);
    gemm_mma<64, NCLS, false, false><<<gemm_blocks, T, SMEM_64_REAL>>>(
        h0, mean, Wneigh2, Wself2, b2, out, nullptr);
}